// round 7
// baseline (speedup 1.0000x reference)
#include <cuda_runtime.h>
#include <cstdint>

#define C_DIM 128
#define K_NB  32
#define MAX_N 100000

// Scratch (no-alloc rule: __device__ globals)
__device__ float g_supports[(size_t)MAX_N * C_DIM];
__device__ float g_Wt[C_DIM * C_DIM];

typedef unsigned long long u64;

__device__ __forceinline__ u64 pack2(float lo, float hi) {
    u64 r;
    asm("mov.b64 %0, {%1, %2};" : "=l"(r) : "f"(lo), "f"(hi));
    return r;
}
__device__ __forceinline__ void fma2(u64 &d, u64 a, u64 b) {
    asm("fma.rn.f32x2 %0, %1, %2, %0;" : "+l"(d) : "l"(a), "l"(b));
}
__device__ __forceinline__ float2 unpack2(u64 v) {
    float2 f;
    asm("mov.b64 {%0, %1}, %2;" : "=f"(f.x), "=f"(f.y) : "l"(v));
    return f;
}

// ---------------------------------------------------------------------------
// Kernel 0: transpose W [C_OUT][C_IN] -> g_Wt [C_IN][C_OUT] (one-time, tiny)
// ---------------------------------------------------------------------------
__global__ void transpose_W(const float* __restrict__ W) {
    int i = blockIdx.x * 256 + threadIdx.x;
    if (i < C_DIM * C_DIM) {
        int col = i >> 7;     // C_OUT index
        int c   = i & 127;    // C_IN index
        g_Wt[c * C_DIM + col] = W[i];
    }
}

// ---------------------------------------------------------------------------
// Kernel 1: supports = leaky_relu(word_vec @ W^T + b, 0.2)
// Writes both d_out (final value for non-src rows) and g_supports (stable
// pre-scatter copy for the aggregation kernel).
//
// blockDim (32, 8): warp ty owns 8 rows; lane tx owns cols 4tx..4tx+3.
// Inner product over c uses packed fp32x2 FMA (FFMA2) for 2x fp32 throughput.
// Shared: Ws = W transposed [c][col] (64KB), xs = 64-row x tile (32KB).
// ---------------------------------------------------------------------------
__global__ __launch_bounds__(256) void proj_kernel(
    const float* __restrict__ x,
    const float* __restrict__ bias,
    float* __restrict__ out,
    int N)
{
    extern __shared__ float smem[];
    float* Ws = smem;                       // [128][128]  (c-major, col fast)
    float* xs = smem + C_DIM * C_DIM;       // [64][128]

    const int tx  = threadIdx.x;
    const int ty  = threadIdx.y;
    const int tid = ty * 32 + tx;
    const int rowBase = blockIdx.x * 64;

    // Load transposed W: linear copy, coalesced + conflict-free.
    #pragma unroll
    for (int i = tid; i < (C_DIM * C_DIM) / 4; i += 256)
        ((float4*)Ws)[i] = ((const float4*)g_Wt)[i];

    // Load 64-row x tile (float4 coalesced, zero-pad tail).
    #pragma unroll
    for (int i = tid; i < 64 * 32; i += 256) {
        int r  = i >> 5;
        int c4 = i & 31;
        int row = rowBase + r;
        float4 v = make_float4(0.f, 0.f, 0.f, 0.f);
        if (row < N) v = ((const float4*)(x + (size_t)row * C_DIM))[c4];
        ((float4*)(xs + r * C_DIM))[c4] = v;
    }
    __syncthreads();

    float4 bv = ((const float4*)bias)[tx];   // b[4tx .. 4tx+3]
    u64 acc[8][2];
    #pragma unroll
    for (int r = 0; r < 8; r++) {
        acc[r][0] = pack2(bv.x, bv.y);
        acc[r][1] = pack2(bv.z, bv.w);
    }

    const float* xrow = xs + (ty * 8) * C_DIM;
    #pragma unroll 8
    for (int c = 0; c < C_DIM; c++) {
        // cols 4tx..4tx+3 of W-transposed row c, as two packed f32x2
        ulonglong2 w = ((const ulonglong2*)Ws)[c * 32 + tx];
        #pragma unroll
        for (int r = 0; r < 8; r++) {
            float xv = xrow[r * C_DIM + c];      // LDS broadcast
            u64 xd = pack2(xv, xv);
            fma2(acc[r][0], w.x, xd);
            fma2(acc[r][1], w.y, xd);
        }
    }

    #pragma unroll
    for (int r = 0; r < 8; r++) {
        int row = rowBase + ty * 8 + r;
        if (row < N) {
            float2 a = unpack2(acc[r][0]);
            float2 b2 = unpack2(acc[r][1]);
            float4 o;
            o.x = a.x  > 0.f ? a.x  : 0.2f * a.x;
            o.y = a.y  > 0.f ? a.y  : 0.2f * a.y;
            o.z = b2.x > 0.f ? b2.x : 0.2f * b2.x;
            o.w = b2.y > 0.f ? b2.y : 0.2f * b2.y;
            ((float4*)(out        + (size_t)row * C_DIM))[tx] = o;
            ((float4*)(g_supports + (size_t)row * C_DIM))[tx] = o;
        }
    }
}

// ---------------------------------------------------------------------------
// Kernel 2: fused scores -> mask -> softmax -> aggregation -> scatter.
// One block (128 threads = 4 warps) per source s.
//   Phase 1: warp w computes dots for neighbors 8w..8w+7 (float4 + shfl reduce)
//   Phase 2: warp 0 does the 32-wide softmax
//   Phase 3: thread t = channel t accumulates sum_k p_k * supports[nb_k][t]
// All gathered rows are L2-resident (word_vec + supports = 102MB < 126MB L2).
// NOTE: indices arrive from the harness as int32 (harness materializes all
// integer inputs as int32; reading them as int64 was the round-6 OOB crash).
// ---------------------------------------------------------------------------
__global__ __launch_bounds__(128) void att_kernel(
    const float* __restrict__ wv,
    const int* __restrict__ src_idx,
    const int* __restrict__ neigh,
    const int* __restrict__ mask,
    float* __restrict__ out,
    int S)
{
    __shared__ float sc[K_NB];
    __shared__ int   nb[K_NB];

    const int s    = blockIdx.x;
    const int tid  = threadIdx.x;
    const int w    = tid >> 5;
    const int lane = tid & 31;

    const int src = src_idx[s];
    const float4 q = ((const float4*)(wv + (size_t)src * C_DIM))[lane];

    #pragma unroll
    for (int kk = 0; kk < 8; kk++) {
        int k = w * 8 + kk;
        int n = neigh[(size_t)s * K_NB + k];
        float4 kv = ((const float4*)(wv + (size_t)n * C_DIM))[lane];
        float p = q.x * kv.x + q.y * kv.y + q.z * kv.z + q.w * kv.w;
        p += __shfl_xor_sync(0xffffffffu, p, 16);
        p += __shfl_xor_sync(0xffffffffu, p, 8);
        p += __shfl_xor_sync(0xffffffffu, p, 4);
        p += __shfl_xor_sync(0xffffffffu, p, 2);
        p += __shfl_xor_sync(0xffffffffu, p, 1);
        if (lane == 0) {
            sc[k] = (mask[(size_t)s * K_NB + k] == 1) ? p * 5.0f : -1e6f;
            nb[k] = n;
        }
    }
    __syncthreads();

    if (tid < 32) {
        float v = sc[tid];
        float m = v;
        m = fmaxf(m, __shfl_xor_sync(0xffffffffu, m, 16));
        m = fmaxf(m, __shfl_xor_sync(0xffffffffu, m, 8));
        m = fmaxf(m, __shfl_xor_sync(0xffffffffu, m, 4));
        m = fmaxf(m, __shfl_xor_sync(0xffffffffu, m, 2));
        m = fmaxf(m, __shfl_xor_sync(0xffffffffu, m, 1));
        float e = __expf(v - m);
        float sum = e;
        sum += __shfl_xor_sync(0xffffffffu, sum, 16);
        sum += __shfl_xor_sync(0xffffffffu, sum, 8);
        sum += __shfl_xor_sync(0xffffffffu, sum, 4);
        sum += __shfl_xor_sync(0xffffffffu, sum, 2);
        sum += __shfl_xor_sync(0xffffffffu, sum, 1);
        sc[tid] = e / sum;
    }
    __syncthreads();

    float acc = 0.f;
    #pragma unroll
    for (int k = 0; k < K_NB; k++) {
        acc = fmaf(sc[k], g_supports[(size_t)nb[k] * C_DIM + tid], acc);
    }
    out[(size_t)src * C_DIM + tid] = acc;
}

// ---------------------------------------------------------------------------
extern "C" void kernel_launch(void* const* d_in, const int* in_sizes, int n_in,
                              void* d_out, int out_size)
{
    const float* word_vec = (const float*)d_in[0];
    const int*   src_idx  = (const int*)d_in[1];   // int32 from harness
    const int*   neighs   = (const int*)d_in[2];   // int32 from harness
    const int*   src_mask = (const int*)d_in[3];
    const float* W        = (const float*)d_in[4];
    const float* b        = (const float*)d_in[5];
    float*       out      = (float*)d_out;

    const int N = in_sizes[0] / C_DIM;
    const int S = in_sizes[1];

    cudaFuncSetAttribute(proj_kernel,
                         cudaFuncAttributeMaxDynamicSharedMemorySize, 98304);

    transpose_W<<<(C_DIM * C_DIM + 255) / 256, 256>>>(W);

    dim3 blk(32, 8);
    proj_kernel<<<(N + 63) / 64, blk, 98304>>>(word_vec, b, out, N);

    att_kernel<<<S, 128>>>(word_vec, src_idx, neighs, src_mask, out, S);
}

// round 9
// speedup vs baseline: 1.0004x; 1.0004x over previous
#include <cuda_runtime.h>
#include <cstdint>

#define C_DIM 128
#define K_NB  32
#define MAX_N 100000
#define WS_STRIDE 130   // padded smem row stride for W (floats); odd*2 => 2-way LDS.64 conflicts only

// Scratch (no-alloc rule: __device__ globals)
__device__ float g_supports[(size_t)MAX_N * C_DIM];

typedef unsigned long long u64;

__device__ __forceinline__ u64 pack2(float lo, float hi) {
    u64 r;
    asm("mov.b64 %0, {%1, %2};" : "=l"(r) : "f"(lo), "f"(hi));
    return r;
}
__device__ __forceinline__ void fma2(u64 &d, u64 a, u64 b) {
    asm("fma.rn.f32x2 %0, %1, %2, %0;" : "+l"(d) : "l"(a), "l"(b));
}
__device__ __forceinline__ float2 unpack2(u64 v) {
    float2 f;
    asm("mov.b64 {%0, %1}, %2;" : "=f"(f.x), "=f"(f.y) : "l"(v));
    return f;
}

// ---------------------------------------------------------------------------
// Kernel 1: supports = leaky_relu(word_vec @ W^T + b, 0.2)
// K-packed FFMA2: accumulator lane0 holds even-c partials, lane1 odd-c.
// W stays ROW-MAJOR (no transpose kernel): w-pair (W[col][c],W[col][c+1]) is
// one LDS.64; x-pair is one broadcast LDS.64. Lane tx owns cols tx+32m.
// Shared: Ws [128][130] (65KB) + xs [64][128] (32KB); xs reused as the
// output staging tile so global stores remain float4-coalesced.
// ---------------------------------------------------------------------------
__global__ __launch_bounds__(256) void proj_kernel(
    const float* __restrict__ x,
    const float* __restrict__ W,
    const float* __restrict__ bias,
    float* __restrict__ out,
    int N)
{
    extern __shared__ float smem[];
    float* Ws = smem;                         // [128][WS_STRIDE]
    float* xs = smem + C_DIM * WS_STRIDE;     // [64][128]

    const int tx  = threadIdx.x;
    const int ty  = threadIdx.y;
    const int tid = ty * 32 + tx;
    const int rowBase = blockIdx.x * 64;

    // Load W row-major into padded smem (float2 stores, 8B-aligned).
    #pragma unroll
    for (int i = tid; i < C_DIM * 32; i += 256) {
        int col = i >> 5;
        int c4  = i & 31;
        float4 v = ((const float4*)(W + (size_t)col * C_DIM))[c4];
        float2* dst = (float2*)(Ws + col * WS_STRIDE + c4 * 4);
        dst[0] = make_float2(v.x, v.y);
        dst[1] = make_float2(v.z, v.w);
    }

    // Load 64-row x tile (float4 coalesced, zero-pad tail).
    #pragma unroll
    for (int i = tid; i < 64 * 32; i += 256) {
        int r  = i >> 5;
        int c4 = i & 31;
        int row = rowBase + r;
        float4 v = make_float4(0.f, 0.f, 0.f, 0.f);
        if (row < N) v = ((const float4*)(x + (size_t)row * C_DIM))[c4];
        ((float4*)(xs + r * C_DIM))[c4] = v;
    }
    __syncthreads();

    u64 acc[8][4];
    #pragma unroll
    for (int r = 0; r < 8; r++)
        #pragma unroll
        for (int m = 0; m < 4; m++) acc[r][m] = 0ull;

    const float* xrow = xs + (ty * 8) * C_DIM;
    const float* wp   = Ws + tx * WS_STRIDE;

    #pragma unroll 4
    for (int c2 = 0; c2 < 64; c2++) {
        u64 w0 = *(const u64*)(wp + 0 * 32 * WS_STRIDE + 2 * c2);
        u64 w1 = *(const u64*)(wp + 1 * 32 * WS_STRIDE + 2 * c2);
        u64 w2 = *(const u64*)(wp + 2 * 32 * WS_STRIDE + 2 * c2);
        u64 w3 = *(const u64*)(wp + 3 * 32 * WS_STRIDE + 2 * c2);
        #pragma unroll
        for (int r = 0; r < 8; r++) {
            u64 xv = *(const u64*)(xrow + r * C_DIM + 2 * c2);  // broadcast
            fma2(acc[r][0], w0, xv);
            fma2(acc[r][1], w1, xv);
            fma2(acc[r][2], w2, xv);
            fma2(acc[r][3], w3, xv);
        }
    }
    __syncthreads();   // done reading xs; reuse as output staging

    float bv[4];
    #pragma unroll
    for (int m = 0; m < 4; m++) bv[m] = bias[tx + 32 * m];

    float* res = xs;   // [64][128]
    #pragma unroll
    for (int r = 0; r < 8; r++) {
        #pragma unroll
        for (int m = 0; m < 4; m++) {
            float2 v = unpack2(acc[r][m]);
            float s = v.x + v.y + bv[m];
            res[(ty * 8 + r) * C_DIM + tx + 32 * m] = s > 0.f ? s : 0.2f * s;
        }
    }
    __syncthreads();

    // Coalesced float4 stores to both buffers.
    #pragma unroll
    for (int i = tid; i < 64 * 32; i += 256) {
        int r  = i >> 5;
        int c4 = i & 31;
        int row = rowBase + r;
        if (row < N) {
            float4 v = ((const float4*)(res + r * C_DIM))[c4];
            ((float4*)(out        + (size_t)row * C_DIM))[c4] = v;
            ((float4*)(g_supports + (size_t)row * C_DIM))[c4] = v;
        }
    }
}

// ---------------------------------------------------------------------------
// Kernel 2: fused scores -> mask -> softmax -> aggregation -> scatter.
// One block (128 threads = 4 warps) per source s.
// Masked-out neighbors are SKIPPED entirely (their softmax weight is exactly
// 0 in fp32, identical to the reference's exp underflow), halving both the
// word_vec dot gathers and the supports gathers. Mask branch is warp-uniform.
// All-masked rows fall back to uniform 1/32 over all neighbors (= reference).
// ---------------------------------------------------------------------------
__global__ __launch_bounds__(128) void att_kernel(
    const float* __restrict__ wv,
    const int* __restrict__ src_idx,
    const int* __restrict__ neigh,
    const int* __restrict__ mask,
    float* __restrict__ out,
    int S)
{
    __shared__ float sc[K_NB];
    __shared__ int   nb[K_NB];
    __shared__ float p_act[K_NB];
    __shared__ int   nb_act[K_NB];
    __shared__ int   s_cnt;

    const int s    = blockIdx.x;
    const int tid  = threadIdx.x;
    const int w    = tid >> 5;
    const int lane = tid & 31;
    const int k0   = w * 8;

    const int src = src_idx[s];
    const float4 q = ((const float4*)(wv + (size_t)src * C_DIM))[lane];

    // lanes 0..7 fetch this warp's 8 neighbor indices + masks
    int myn = 0, mym = 0;
    if (lane < 8) {
        myn = neigh[(size_t)s * K_NB + k0 + lane];
        mym = mask [(size_t)s * K_NB + k0 + lane];
        nb[k0 + lane] = myn;
    }

    float p[8];
    int   nk[8], mk[8];
    #pragma unroll
    for (int kk = 0; kk < 8; kk++) {
        nk[kk] = __shfl_sync(0xffffffffu, myn, kk);
        mk[kk] = __shfl_sync(0xffffffffu, mym, kk);
        if (mk[kk]) {   // warp-uniform branch: skip load for masked neighbors
            float4 kv = ((const float4*)(wv + (size_t)nk[kk] * C_DIM))[lane];
            p[kk] = q.x * kv.x + q.y * kv.y + q.z * kv.z + q.w * kv.w;
        } else {
            p[kk] = 0.f;
        }
    }
    // interleaved butterfly reduce (8 chains pipelined per level)
    #pragma unroll
    for (int lvl = 16; lvl > 0; lvl >>= 1) {
        #pragma unroll
        for (int kk = 0; kk < 8; kk++)
            p[kk] += __shfl_xor_sync(0xffffffffu, p[kk], lvl);
    }
    if (lane == 0) {
        #pragma unroll
        for (int kk = 0; kk < 8; kk++)
            sc[k0 + kk] = mk[kk] ? p[kk] * 5.0f : -1e6f;
    }
    __syncthreads();

    // warp 0: softmax over active entries + compaction
    if (tid < 32) {
        float v = sc[tid];
        bool act = (v != -1e6f);
        unsigned bal = __ballot_sync(0xffffffffu, act);
        int cnt = __popc(bal);
        if (cnt == 0) {
            p_act[tid]  = 1.0f / 32.0f;
            nb_act[tid] = nb[tid];
            if (tid == 0) s_cnt = 32;
        } else {
            float m = v;
            m = fmaxf(m, __shfl_xor_sync(0xffffffffu, m, 16));
            m = fmaxf(m, __shfl_xor_sync(0xffffffffu, m, 8));
            m = fmaxf(m, __shfl_xor_sync(0xffffffffu, m, 4));
            m = fmaxf(m, __shfl_xor_sync(0xffffffffu, m, 2));
            m = fmaxf(m, __shfl_xor_sync(0xffffffffu, m, 1));
            float e = act ? __expf(v - m) : 0.f;
            float sum = e;
            sum += __shfl_xor_sync(0xffffffffu, sum, 16);
            sum += __shfl_xor_sync(0xffffffffu, sum, 8);
            sum += __shfl_xor_sync(0xffffffffu, sum, 4);
            sum += __shfl_xor_sync(0xffffffffu, sum, 2);
            sum += __shfl_xor_sync(0xffffffffu, sum, 1);
            if (act) {
                int pos = __popc(bal & ((1u << tid) - 1u));
                p_act[pos]  = e / sum;
                nb_act[pos] = nb[tid];
            }
            if (tid == 0) s_cnt = cnt;
        }
    }
    __syncthreads();

    // aggregation over compacted active neighbors only
    const int cnt = s_cnt;
    float acc = 0.f;
    int k = 0;
    for (; k + 4 <= cnt; k += 4) {
        float a0 = g_supports[(size_t)nb_act[k + 0] * C_DIM + tid];
        float a1 = g_supports[(size_t)nb_act[k + 1] * C_DIM + tid];
        float a2 = g_supports[(size_t)nb_act[k + 2] * C_DIM + tid];
        float a3 = g_supports[(size_t)nb_act[k + 3] * C_DIM + tid];
        acc = fmaf(p_act[k + 0], a0, acc);
        acc = fmaf(p_act[k + 1], a1, acc);
        acc = fmaf(p_act[k + 2], a2, acc);
        acc = fmaf(p_act[k + 3], a3, acc);
    }
    for (; k < cnt; k++)
        acc = fmaf(p_act[k], g_supports[(size_t)nb_act[k] * C_DIM + tid], acc);

    out[(size_t)src * C_DIM + tid] = acc;
}

// ---------------------------------------------------------------------------
extern "C" void kernel_launch(void* const* d_in, const int* in_sizes, int n_in,
                              void* d_out, int out_size)
{
    const float* word_vec = (const float*)d_in[0];
    const int*   src_idx  = (const int*)d_in[1];   // int32 from harness
    const int*   neighs   = (const int*)d_in[2];   // int32 from harness
    const int*   src_mask = (const int*)d_in[3];
    const float* W        = (const float*)d_in[4];
    const float* b        = (const float*)d_in[5];
    float*       out      = (float*)d_out;

    const int N = in_sizes[0] / C_DIM;
    const int S = in_sizes[1];

    const int smem_bytes = (C_DIM * WS_STRIDE + 64 * C_DIM) * sizeof(float); // 99328
    cudaFuncSetAttribute(proj_kernel,
                         cudaFuncAttributeMaxDynamicSharedMemorySize, smem_bytes);

    dim3 blk(32, 8);
    proj_kernel<<<(N + 63) / 64, blk, smem_bytes>>>(word_vec, W, b, out, N);

    att_kernel<<<S, 128>>>(word_vec, src_idx, neighs, src_mask, out, S);
}